// round 11
// baseline (speedup 1.0000x reference)
#include <cuda_runtime.h>

typedef unsigned long long u64;
typedef unsigned int u32;

#define B_TOT   256
#define IN_CAPS 1152
#define KDIM    8
#define NCAPS   10
#define DDIM    16
#define P0CH    36              /* pass0 i-chunks (32 i each)  */
#define SWCH    72              /* sweep i-chunks (16 i each)  */
#define BGROUPS 8
#define SND     (B_TOT*NCAPS*DDIM)      /* 40960 */
#define FDIM    (IN_CAPS*KDIM)          /* 9216  */
#define XELEMS  (IN_CAPS*B_TOT*KDIM)
#define XBLKS   ((FDIM/32)*(B_TOT/32))  /* 2304  */
#define WELEMS  (NCAPS*IN_CAPS*128)
#define WBLKS   ((WELEMS+1023)/1024)
#define XSTRIDE (B_TOT*KDIM)            /* 2048 floats per i */

// ---------------- scratch (static device memory, no allocs) ----------------
__device__ float g_Wt[NCAPS*IN_CAPS*128];            // W transposed: [n][i][k][d]
__device__ float g_xI[XELEMS];                       // x re-laid:   [i][b][k]
__device__ float g_spart[SWCH*SND];                  // per-chunk partial s
__device__ float g_vc[SND];                          // CUMULATIVE v  [b][n][d]
__device__ u64   g_uh[(size_t)NCAPS*IN_CAPS*4*B_TOT];// u_hat fp16: [n][i][dq][b], 4 f16/u64

// ---------------- f32x2 / pack helpers ----------------
__device__ __forceinline__ u64 pk2(float x, float y){
    u64 r; asm("mov.b64 %0,{%1,%2};" : "=l"(r) : "f"(x), "f"(y)); return r;
}
__device__ __forceinline__ u64 pk2u(u32 x, u32 y){
    u64 r; asm("mov.b64 %0,{%1,%2};" : "=l"(r) : "r"(x), "r"(y)); return r;
}
__device__ __forceinline__ void upk2(u64 a, float& x, float& y){
    asm("mov.b64 {%0,%1},%2;" : "=f"(x), "=f"(y) : "l"(a));
}
__device__ __forceinline__ void upk2u(u64 a, u32& x, u32& y){
    asm("mov.b64 {%0,%1},%2;" : "=r"(x), "=r"(y) : "l"(a));
}
__device__ __forceinline__ u64 ffma2(u64 a, u64 b, u64 c){
    u64 d; asm("fma.rn.f32x2 %0,%1,%2,%3;" : "=l"(d) : "l"(a), "l"(b), "l"(c)); return d;
}
__device__ __forceinline__ u64 fmul2(u64 a, u64 b){
    u64 d; asm("mul.rn.f32x2 %0,%1,%2;" : "=l"(d) : "l"(a), "l"(b)); return d;
}
__device__ __forceinline__ u64 fadd2(u64 a, u64 b){
    u64 d; asm("add.rn.f32x2 %0,%1,%2;" : "=l"(d) : "l"(a), "l"(b)); return d;
}
__device__ __forceinline__ u32 smemu32(const void* p){
    u32 a; asm("{ .reg .u64 t; cvta.to.shared.u64 t, %1; cvt.u32.u64 %0, t; }" : "=r"(a) : "l"(p));
    return a;
}
__device__ __forceinline__ void cpasync16(u32 dst, const void* src){
    asm volatile("cp.async.ca.shared.global [%0],[%1],16;" :: "r"(dst), "l"(src));
}
__device__ __forceinline__ void cpcommit(){ asm volatile("cp.async.commit_group;"); }
__device__ __forceinline__ void cpwait1(){ asm volatile("cp.async.wait_group 1;"); }

// f32x2 pair -> f16x2 (low half = even d, high half = odd d)
__device__ __forceinline__ u32 hfp(u64 p){
    float x, y; upk2(p, x, y);
    u32 r; asm("cvt.rn.f16x2.f32 %0, %1, %2;" : "=r"(r) : "f"(y), "f"(x));
    return r;
}
// f16x2 -> f32x2 (even d in low word)
__device__ __forceinline__ u64 expand_h2(u32 hpair){
    float lo, hi;
    asm("{ .reg .f16 a, b;\n\t"
        "  mov.b32 {a, b}, %2;\n\t"
        "  cvt.f32.f16 %0, a;\n\t"
        "  cvt.f32.f16 %1, b; }"
        : "=f"(lo), "=f"(hi) : "r"(hpair));
    return pk2(lo, hi);
}
// u64 of 4 fp16 -> two f32x2 pairs
__device__ __forceinline__ void expand4(u64 r, u64& p0, u64& p1){
    u32 a, b; upk2u(r, a, b);
    p0 = expand_h2(a);
    p1 = expand_h2(b);
}

// half-warp tu: this thread's d-half (hb = h*2) for TWO batches, sharing W loads.
__device__ __forceinline__ void tu_half2(const ulonglong2* __restrict__ wr, int hb,
                                         const float* __restrict__ XL,
                                         const float* __restrict__ XH,
                                         u64* aL, u64* aH){
    #pragma unroll
    for (int k = 0; k < 8; k++){
        u64 xkL = pk2(XL[k], XL[k]);
        u64 xkH = pk2(XH[k], XH[k]);
        ulonglong2 w0 = wr[k*4 + hb];
        ulonglong2 w1 = wr[k*4 + hb + 1];
        if (k == 0){
            aL[0] = fmul2(w0.x, xkL); aL[1] = fmul2(w0.y, xkL);
            aL[2] = fmul2(w1.x, xkL); aL[3] = fmul2(w1.y, xkL);
            aH[0] = fmul2(w0.x, xkH); aH[1] = fmul2(w0.y, xkH);
            aH[2] = fmul2(w1.x, xkH); aH[3] = fmul2(w1.y, xkH);
        } else {
            aL[0] = ffma2(w0.x, xkL, aL[0]); aL[1] = ffma2(w0.y, xkL, aL[1]);
            aL[2] = ffma2(w1.x, xkL, aL[2]); aL[3] = ffma2(w1.y, xkL, aL[3]);
            aH[0] = ffma2(w0.x, xkH, aH[0]); aH[1] = ffma2(w0.y, xkH, aH[1]);
            aH[2] = ffma2(w1.x, xkH, aH[2]); aH[3] = ffma2(w1.y, xkH, aH[3]);
        }
    }
}

// ---------------- prep: x re-layout (coalesced) + W transpose ----------------
__global__ void k_prep(const float* __restrict__ x, const float* __restrict__ W){
    __shared__ float t[32][33];
    int xb = blockIdx.x;
    int tid = threadIdx.x;
    if (xb < XBLKS){
        int f0 = (xb % (FDIM/32)) * 32;
        int b0 = (xb / (FDIM/32)) * 32;
        int b_loc = tid >> 5, f_loc = tid & 31;
        t[b_loc][f_loc] = x[(size_t)(b0 + b_loc) * FDIM + f0 + f_loc];
        __syncthreads();
        int i_loc = tid >> 8;
        int r = tid & 255;
        int b = r >> 3, k = r & 7;
        g_xI[(size_t)(f0/8 + i_loc) * XSTRIDE + (b0 + b) * KDIM + k] = t[b][i_loc*8 + k];
    } else {
        int idx = (xb - XBLKS) * 1024 + tid;
        if (idx < WELEMS){
            int k  = idx & 7;
            int d  = (idx >> 3) & 15;
            int ni = idx >> 7;
            g_Wt[(ni << 7) | (k << 4) | d] = W[idx];
        }
    }
}

// ---------------- pass0: compute u_hat (fp32), accumulate s0, store u_hat fp16 ----
// warp = capsule n, half-warp d-split, 2 batches/thread. grid (36, 8), 2 CTAs/SM.
__global__ void __launch_bounds__(320, 2) k_pass0(){
    __shared__ __align__(16) float ws[2][NCAPS*128];

    const int tid   = threadIdx.x;
    const int n     = tid >> 5;
    const int lane  = tid & 31;
    const int l16   = lane & 15;
    const int h     = lane >> 4;
    const int hb    = h * 2;
    const int chunk = blockIdx.x;
    const int bg    = blockIdx.y;
    const int i0    = chunk * 32;
    const int b_lo  = bg * 32 + l16;
    const int b_hi  = b_lo + 16;

    u64 sL[4], sH[4];
    #pragma unroll
    for (int p = 0; p < 4; p++){ sL[p] = 0ull; sH[p] = 0ull; }

    const float* wsrc = g_Wt + ((size_t)(n*IN_CAPS + i0))*128 + lane*4;
    const u32 wdst0 = smemu32(&ws[0][n*128 + lane*4]);
    const u32 wdst1 = smemu32(&ws[1][n*128 + lane*4]);
    const float* xl = g_xI + (size_t)i0 * XSTRIDE + b_lo * KDIM;
    const float* xh = g_xI + (size_t)i0 * XSTRIDE + b_hi * KDIM;
    // u_hat store base: [n][i][dq][b]; this thread writes dq = 2h, 2h+1
    u64* ub = g_uh + (((size_t)(n*IN_CAPS + i0))*4 + 2*h)*B_TOT + b_lo;

    cpasync16(wdst0, wsrc); cpcommit();
    #pragma unroll 1
    for (int ii = 0; ii < 32; ii++){
        if (ii + 1 < 32) cpasync16((ii & 1) ? wdst0 : wdst1, wsrc + 128);
        cpcommit();
        wsrc += 128;
        cpwait1();
        float4 q0 = *(const float4*)xl, q1 = *(const float4*)(xl + 4);
        float4 r0 = *(const float4*)xh, r1 = *(const float4*)(xh + 4);
        xl += XSTRIDE; xh += XSTRIDE;
        float XL[8] = {q0.x,q0.y,q0.z,q0.w, q1.x,q1.y,q1.z,q1.w};
        float XH[8] = {r0.x,r0.y,r0.z,r0.w, r1.x,r1.y,r1.z,r1.w};
        u64 aL[4], aH[4];
        tu_half2((const ulonglong2*)&ws[ii & 1][n*128], hb, XL, XH, aL, aH);
        #pragma unroll
        for (int p = 0; p < 4; p++){ sL[p] = fadd2(sL[p], aL[p]); sH[p] = fadd2(sH[p], aH[p]); }
        // store fp16 u_hat: dq=2h gets d pairs (aL[0],aL[1]); dq=2h+1 gets (aL[2],aL[3])
        ub[0]           = pk2u(hfp(aL[0]), hfp(aL[1]));
        ub[B_TOT]       = pk2u(hfp(aL[2]), hfp(aL[3]));
        ub[16]          = pk2u(hfp(aH[0]), hfp(aH[1]));
        ub[B_TOT + 16]  = pk2u(hfp(aH[2]), hfp(aH[3]));
        ub += 4*B_TOT;
    }

    // partials into 36-chunk region (slices 0..35)
    float* spL = g_spart + ((size_t)(chunk*B_TOT + b_lo)*NCAPS + n)*DDIM + 8*h;
    float* spH = g_spart + ((size_t)(chunk*B_TOT + b_hi)*NCAPS + n)*DDIM + 8*h;
    ((ulonglong2*)spL)[0] = make_ulonglong2(sL[0], sL[1]);
    ((ulonglong2*)spL)[1] = make_ulonglong2(sL[2], sL[3]);
    ((ulonglong2*)spH)[0] = make_ulonglong2(sH[0], sH[1]);
    ((ulonglong2*)spH)[1] = make_ulonglong2(sH[2], sH[3]);
}

// ---------------- routed sweep: stream fp16 u_hat, softmax, accumulate ----------
// warp = capsule n (10 warps), lane = batch. grid (72, 8) = 576 CTAs, 3 CTAs/SM.
// logit = tu . vc (cumulative v). One barrier per i-step, ping-pong exchange.
__global__ void __launch_bounds__(320, 3) k_sweep(){
    __shared__ float ex[2][NCAPS][32];

    const int tid   = threadIdx.x;
    const int n     = tid >> 5;
    const int lane  = tid & 31;
    const int chunk = blockIdx.x;
    const int bg    = blockIdx.y;
    const int i0    = chunk * 16;
    const int b     = bg * 32 + lane;

    u64 v[8];
    {
        const u64* vp = (const u64*)&g_vc[(b*NCAPS + n)*DDIM];
        #pragma unroll
        for (int p = 0; p < 8; p++) v[p] = vp[p];
    }
    u64 s[8];
    #pragma unroll
    for (int p = 0; p < 8; p++) s[p] = 0ull;

    const u64* up = g_uh + ((size_t)(n*IN_CAPS + i0))*4*B_TOT + b;

    #pragma unroll 1
    for (int ii = 0; ii < 16; ii++){
        u64 r0 = up[0], r1 = up[B_TOT], r2 = up[2*B_TOT], r3 = up[3*B_TOT];
        up += 4*B_TOT;
        u64 tu[8];
        expand4(r0, tu[0], tu[1]);
        expand4(r1, tu[2], tu[3]);
        expand4(r2, tu[4], tu[5]);
        expand4(r3, tu[6], tu[7]);

        u64 d0 = fmul2(tu[0], v[0]);
        #pragma unroll
        for (int p = 1; p < 8; p++) d0 = ffma2(tu[p], v[p], d0);
        float lo, hi; upk2(d0, lo, hi);
        float e = __expf(lo + hi);        // |logit| small: no max-sub needed
        ex[ii & 1][n][lane] = e;
        __syncthreads();                  // single barrier; ping-pong is WAR-safe
        float z01 = ex[ii & 1][0][lane] + ex[ii & 1][1][lane];
        float z23 = ex[ii & 1][2][lane] + ex[ii & 1][3][lane];
        float z45 = ex[ii & 1][4][lane] + ex[ii & 1][5][lane];
        float z67 = ex[ii & 1][6][lane] + ex[ii & 1][7][lane];
        float z89 = ex[ii & 1][8][lane] + ex[ii & 1][9][lane];
        float Z = ((z01 + z23) + (z45 + z67)) + z89;
        float c = __fdividef(e, Z);
        u64 cc = pk2(c, c);
        #pragma unroll
        for (int p = 0; p < 8; p++) s[p] = ffma2(tu[p], cc, s[p]);
    }

    // partials into 72-chunk region
    float* sp = g_spart + ((size_t)(chunk*B_TOT + b)*NCAPS + n)*DDIM;
    #pragma unroll
    for (int q = 0; q < 4; q++)
        ((ulonglong2*)sp)[q] = make_ulonglong2(s[2*q], s[2*q+1]);
}

// ---------------- reduce partials + squash (2 warps per (b,n)) ----------------
// NJ=9 -> 36 chunks (pass0), NJ=18 -> 72 chunks (sweeps)
// MODE 0: vc = v ; MODE 1: vc += v ; MODE 2: out = v
template<int MODE, int NJ>
__global__ void k_reduce(float* __restrict__ out, float scale){
    __shared__ float red[4][2][16];
    const int tid  = threadIdx.x;
    const int wid  = tid >> 5;
    const int lane = tid & 31;
    const int pib  = wid >> 1;
    const int half = wid & 1;
    const int pair = blockIdx.x * 4 + pib;     // (b,n) in [0, 2560)
    const int d    = lane & 15;
    const int hh   = lane >> 4;
    const size_t base = (size_t)pair * DDIM + d;

    float s = 0.f;
    #pragma unroll
    for (int j = 0; j < NJ; j++)
        s += g_spart[(size_t)(half*2 + hh + 4*j) * SND + base];
    s += __shfl_xor_sync(0xffffffffu, s, 16);
    if (lane < 16) red[pib][half][d] = s;
    __syncthreads();
    if (half == 0){
        float st = (red[pib][0][d] + red[pib][1][d]) * scale;
        float sq = st * st;
        sq += __shfl_xor_sync(0xffffffffu, sq, 1);
        sq += __shfl_xor_sync(0xffffffffu, sq, 2);
        sq += __shfl_xor_sync(0xffffffffu, sq, 4);
        sq += __shfl_xor_sync(0xffffffffu, sq, 8);
        float nrm = sqrtf(sq);
        float vv = (sq / (1.0f + sq)) * (st / (nrm + 1e-8f));
        if (lane < 16){
            if (MODE == 0)      g_vc[base] = vv;
            else if (MODE == 1) g_vc[base] += vv;
            else                out[base] = vv;
        }
    }
}

// ---------------- launch ----------------
extern "C" void kernel_launch(void* const* d_in, const int* in_sizes, int n_in,
                              void* d_out, int out_size){
    const float* x = (const float*)d_in[0];
    const float* W = (const float*)d_in[1];
    if (n_in >= 2 && in_sizes[0] == WELEMS){   // defensive order swap
        const float* t = x; x = W; W = t;
    }
    float* out = (float*)d_out;

    k_prep<<<XBLKS + WBLKS, 1024>>>(x, W);

    const int RB = (B_TOT*NCAPS)/4;    // 640 blocks

    k_pass0<<<dim3(P0CH, BGROUPS), 320>>>();
    k_reduce<0, 9><<<RB, 256>>>(nullptr, 0.1f);   // c = softmax(0) = 1/10

    dim3 sg(SWCH, BGROUPS);
    k_sweep<<<sg, 320>>>();
    k_reduce<1, 18><<<RB, 256>>>(nullptr, 1.0f);

    k_sweep<<<sg, 320>>>();
    k_reduce<1, 18><<<RB, 256>>>(nullptr, 1.0f);

    k_sweep<<<sg, 320>>>();
    k_reduce<2, 18><<<RB, 256>>>(out, 1.0f);
}

// round 12
// speedup vs baseline: 1.1249x; 1.1249x over previous
#include <cuda_runtime.h>

typedef unsigned long long u64;
typedef unsigned int u32;

#define B_TOT   256
#define IN_CAPS 1152
#define KDIM    8
#define NCAPS   10
#define DDIM    16
#define P0CH    36              /* pass0 i-chunks (32 i each)  */
#define SWCH    72              /* sweep i-chunks (16 i each)  */
#define BGROUPS 8
#define SND     (B_TOT*NCAPS*DDIM)      /* 40960 */
#define FDIM    (IN_CAPS*KDIM)          /* 9216  */
#define XELEMS  (IN_CAPS*B_TOT*KDIM)
#define XBLKS   ((FDIM/32)*(B_TOT/32))  /* 2304  */
#define WELEMS  (NCAPS*IN_CAPS*128)
#define WBLKS   ((WELEMS+1023)/1024)
#define XSTRIDE (B_TOT*KDIM)            /* 2048 floats per i */

// ---------------- scratch (static device memory, no allocs) ----------------
__device__ float g_Wt[NCAPS*IN_CAPS*128];            // W transposed: [n][i][k][d]
__device__ float g_xI[XELEMS];                       // x re-laid:   [i][b][k]
__device__ float g_spart[SWCH*SND];                  // per-chunk partial s
__device__ float g_vc[SND];                          // CUMULATIVE v  [b][n][d]
__device__ u64   g_uh[(size_t)NCAPS*IN_CAPS*B_TOT*4];// u_hat fp16: [n][i][b][dq] (32B per (n,i,b))

// ---------------- f32x2 / pack helpers ----------------
__device__ __forceinline__ u64 pk2(float x, float y){
    u64 r; asm("mov.b64 %0,{%1,%2};" : "=l"(r) : "f"(x), "f"(y)); return r;
}
__device__ __forceinline__ u64 pk2u(u32 x, u32 y){
    u64 r; asm("mov.b64 %0,{%1,%2};" : "=l"(r) : "r"(x), "r"(y)); return r;
}
__device__ __forceinline__ void upk2(u64 a, float& x, float& y){
    asm("mov.b64 {%0,%1},%2;" : "=f"(x), "=f"(y) : "l"(a));
}
__device__ __forceinline__ void upk2u(u64 a, u32& x, u32& y){
    asm("mov.b64 {%0,%1},%2;" : "=r"(x), "=r"(y) : "l"(a));
}
__device__ __forceinline__ u64 ffma2(u64 a, u64 b, u64 c){
    u64 d; asm("fma.rn.f32x2 %0,%1,%2,%3;" : "=l"(d) : "l"(a), "l"(b), "l"(c)); return d;
}
__device__ __forceinline__ u64 fmul2(u64 a, u64 b){
    u64 d; asm("mul.rn.f32x2 %0,%1,%2;" : "=l"(d) : "l"(a), "l"(b)); return d;
}
__device__ __forceinline__ u64 fadd2(u64 a, u64 b){
    u64 d; asm("add.rn.f32x2 %0,%1,%2;" : "=l"(d) : "l"(a), "l"(b)); return d;
}
__device__ __forceinline__ u32 smemu32(const void* p){
    u32 a; asm("{ .reg .u64 t; cvta.to.shared.u64 t, %1; cvt.u32.u64 %0, t; }" : "=r"(a) : "l"(p));
    return a;
}
__device__ __forceinline__ void cpasync16(u32 dst, const void* src){
    asm volatile("cp.async.ca.shared.global [%0],[%1],16;" :: "r"(dst), "l"(src));
}
__device__ __forceinline__ void cpcommit(){ asm volatile("cp.async.commit_group;"); }
__device__ __forceinline__ void cpwait1(){ asm volatile("cp.async.wait_group 1;"); }

// f32x2 pair -> f16x2 (low half = even d, high half = odd d)
__device__ __forceinline__ u32 hfp(u64 p){
    float x, y; upk2(p, x, y);
    u32 r; asm("cvt.rn.f16x2.f32 %0, %1, %2;" : "=r"(r) : "f"(y), "f"(x));
    return r;
}
// f16x2 -> f32x2 (even d in low word)
__device__ __forceinline__ u64 expand_h2(u32 hpair){
    float lo, hi;
    asm("{ .reg .f16 a, b;\n\t"
        "  mov.b32 {a, b}, %2;\n\t"
        "  cvt.f32.f16 %0, a;\n\t"
        "  cvt.f32.f16 %1, b; }"
        : "=f"(lo), "=f"(hi) : "r"(hpair));
    return pk2(lo, hi);
}
// u64 of 4 fp16 -> two f32x2 pairs
__device__ __forceinline__ void expand4(u64 r, u64& p0, u64& p1){
    u32 a, b; upk2u(r, a, b);
    p0 = expand_h2(a);
    p1 = expand_h2(b);
}

// half-warp tu: this thread's d-half (hb = h*2) for TWO batches, sharing W loads.
__device__ __forceinline__ void tu_half2(const ulonglong2* __restrict__ wr, int hb,
                                         const float* __restrict__ XL,
                                         const float* __restrict__ XH,
                                         u64* aL, u64* aH){
    #pragma unroll
    for (int k = 0; k < 8; k++){
        u64 xkL = pk2(XL[k], XL[k]);
        u64 xkH = pk2(XH[k], XH[k]);
        ulonglong2 w0 = wr[k*4 + hb];
        ulonglong2 w1 = wr[k*4 + hb + 1];
        if (k == 0){
            aL[0] = fmul2(w0.x, xkL); aL[1] = fmul2(w0.y, xkL);
            aL[2] = fmul2(w1.x, xkL); aL[3] = fmul2(w1.y, xkL);
            aH[0] = fmul2(w0.x, xkH); aH[1] = fmul2(w0.y, xkH);
            aH[2] = fmul2(w1.x, xkH); aH[3] = fmul2(w1.y, xkH);
        } else {
            aL[0] = ffma2(w0.x, xkL, aL[0]); aL[1] = ffma2(w0.y, xkL, aL[1]);
            aL[2] = ffma2(w1.x, xkL, aL[2]); aL[3] = ffma2(w1.y, xkL, aL[3]);
            aH[0] = ffma2(w0.x, xkH, aH[0]); aH[1] = ffma2(w0.y, xkH, aH[1]);
            aH[2] = ffma2(w1.x, xkH, aH[2]); aH[3] = ffma2(w1.y, xkH, aH[3]);
        }
    }
}

// ---------------- prep: x re-layout (coalesced) + W transpose ----------------
__global__ void k_prep(const float* __restrict__ x, const float* __restrict__ W){
    __shared__ float t[32][33];
    int xb = blockIdx.x;
    int tid = threadIdx.x;
    if (xb < XBLKS){
        int f0 = (xb % (FDIM/32)) * 32;
        int b0 = (xb / (FDIM/32)) * 32;
        int b_loc = tid >> 5, f_loc = tid & 31;
        t[b_loc][f_loc] = x[(size_t)(b0 + b_loc) * FDIM + f0 + f_loc];
        __syncthreads();
        int i_loc = tid >> 8;
        int r = tid & 255;
        int b = r >> 3, k = r & 7;
        g_xI[(size_t)(f0/8 + i_loc) * XSTRIDE + (b0 + b) * KDIM + k] = t[b][i_loc*8 + k];
    } else {
        int idx = (xb - XBLKS) * 1024 + tid;
        if (idx < WELEMS){
            int k  = idx & 7;
            int d  = (idx >> 3) & 15;
            int ni = idx >> 7;
            g_Wt[(ni << 7) | (k << 4) | d] = W[idx];
        }
    }
}

// ---------------- pass0: compute u_hat (fp32), accumulate s0, store u_hat fp16 ----
// warp = capsule n, half-warp d-split, 2 batches/thread. grid (36, 8), 2 CTAs/SM.
__global__ void __launch_bounds__(320, 2) k_pass0(){
    __shared__ __align__(16) float ws[2][NCAPS*128];

    const int tid   = threadIdx.x;
    const int n     = tid >> 5;
    const int lane  = tid & 31;
    const int l16   = lane & 15;
    const int h     = lane >> 4;
    const int hb    = h * 2;
    const int chunk = blockIdx.x;
    const int bg    = blockIdx.y;
    const int i0    = chunk * 32;
    const int b_lo  = bg * 32 + l16;
    const int b_hi  = b_lo + 16;

    u64 sL[4], sH[4];
    #pragma unroll
    for (int p = 0; p < 4; p++){ sL[p] = 0ull; sH[p] = 0ull; }

    const float* wsrc = g_Wt + ((size_t)(n*IN_CAPS + i0))*128 + lane*4;
    const u32 wdst0 = smemu32(&ws[0][n*128 + lane*4]);
    const u32 wdst1 = smemu32(&ws[1][n*128 + lane*4]);
    const float* xl = g_xI + (size_t)i0 * XSTRIDE + b_lo * KDIM;
    const float* xh = g_xI + (size_t)i0 * XSTRIDE + b_hi * KDIM;
    // u_hat [n][i][b][dq]; this thread writes dq = {2h, 2h+1} for b_lo and b_hi
    u64* ub = g_uh + ((size_t)(n*IN_CAPS + i0) * B_TOT + b_lo) * 4 + 2*h;

    cpasync16(wdst0, wsrc); cpcommit();
    #pragma unroll 1
    for (int ii = 0; ii < 32; ii++){
        if (ii + 1 < 32) cpasync16((ii & 1) ? wdst0 : wdst1, wsrc + 128);
        cpcommit();
        wsrc += 128;
        cpwait1();
        float4 q0 = *(const float4*)xl, q1 = *(const float4*)(xl + 4);
        float4 r0 = *(const float4*)xh, r1 = *(const float4*)(xh + 4);
        xl += XSTRIDE; xh += XSTRIDE;
        float XL[8] = {q0.x,q0.y,q0.z,q0.w, q1.x,q1.y,q1.z,q1.w};
        float XH[8] = {r0.x,r0.y,r0.z,r0.w, r1.x,r1.y,r1.z,r1.w};
        u64 aL[4], aH[4];
        tu_half2((const ulonglong2*)&ws[ii & 1][n*128], hb, XL, XH, aL, aH);
        #pragma unroll
        for (int p = 0; p < 4; p++){ sL[p] = fadd2(sL[p], aL[p]); sH[p] = fadd2(sH[p], aH[p]); }
        // fp16 stores: one STG.128 per batch (dq pair contiguous)
        ((ulonglong2*)ub)[0]      = make_ulonglong2(pk2u(hfp(aL[0]), hfp(aL[1])),
                                                    pk2u(hfp(aL[2]), hfp(aL[3])));
        ((ulonglong2*)(ub + 64))[0] = make_ulonglong2(pk2u(hfp(aH[0]), hfp(aH[1])),
                                                      pk2u(hfp(aH[2]), hfp(aH[3])));
        ub += (size_t)B_TOT * 4;
    }

    // partials into 36-chunk region (slices 0..35)
    float* spL = g_spart + ((size_t)(chunk*B_TOT + b_lo)*NCAPS + n)*DDIM + 8*h;
    float* spH = g_spart + ((size_t)(chunk*B_TOT + b_hi)*NCAPS + n)*DDIM + 8*h;
    ((ulonglong2*)spL)[0] = make_ulonglong2(sL[0], sL[1]);
    ((ulonglong2*)spL)[1] = make_ulonglong2(sL[2], sL[3]);
    ((ulonglong2*)spH)[0] = make_ulonglong2(sH[0], sH[1]);
    ((ulonglong2*)spH)[1] = make_ulonglong2(sH[2], sH[3]);
}

// ---------------- routed sweep: stream fp16 u_hat, softmax, accumulate ----------
// warp = capsule n, lane = batch. grid (72, 8) = 576 CTAs, 3 CTAs/SM.
// 2x LDG.128 per i-step, pipelined one step ahead across the barrier.
// Raw loaded regs are expanded TWICE (dot, then accumulate) to keep regs < 68.
__global__ void __launch_bounds__(320, 3) k_sweep(){
    __shared__ float ex[2][NCAPS][32];

    const int tid   = threadIdx.x;
    const int n     = tid >> 5;
    const int lane  = tid & 31;
    const int chunk = blockIdx.x;
    const int bg    = blockIdx.y;
    const int i0    = chunk * 16;
    const int b     = bg * 32 + lane;

    u64 v[8];
    {
        const u64* vp = (const u64*)&g_vc[(b*NCAPS + n)*DDIM];
        #pragma unroll
        for (int p = 0; p < 8; p++) v[p] = vp[p];
    }
    u64 s[8];
    #pragma unroll
    for (int p = 0; p < 8; p++) s[p] = 0ull;

    const ulonglong2* up =
        (const ulonglong2*)(g_uh + ((size_t)(n*IN_CAPS + i0) * B_TOT + b) * 4);
    ulonglong2 rA = up[0], rB = up[1];      // 32 B of u_hat for (n, i0, b)

    #pragma unroll 1
    for (int ii = 0; ii < 16; ii++){
        up += (size_t)B_TOT * 2;            // next i
        ulonglong2 nA, nB;
        if (ii + 1 < 16){ nA = up[0]; nB = up[1]; }   // pipelined loads

        // expand #1 for the dot (transient pairs)
        u64 t0, t1;
        expand4(rA.x, t0, t1);
        u64 d0 = fmul2(t0, v[0]); d0 = ffma2(t1, v[1], d0);
        expand4(rA.y, t0, t1);
        d0 = ffma2(t0, v[2], d0); d0 = ffma2(t1, v[3], d0);
        expand4(rB.x, t0, t1);
        d0 = ffma2(t0, v[4], d0); d0 = ffma2(t1, v[5], d0);
        expand4(rB.y, t0, t1);
        d0 = ffma2(t0, v[6], d0); d0 = ffma2(t1, v[7], d0);

        float lo, hi; upk2(d0, lo, hi);
        float e = __expf(lo + hi);          // |logit| small: no max-sub needed
        ex[ii & 1][n][lane] = e;
        __syncthreads();                    // single barrier; ping-pong is WAR-safe
        float z01 = ex[ii & 1][0][lane] + ex[ii & 1][1][lane];
        float z23 = ex[ii & 1][2][lane] + ex[ii & 1][3][lane];
        float z45 = ex[ii & 1][4][lane] + ex[ii & 1][5][lane];
        float z67 = ex[ii & 1][6][lane] + ex[ii & 1][7][lane];
        float z89 = ex[ii & 1][8][lane] + ex[ii & 1][9][lane];
        float Z = ((z01 + z23) + (z45 + z67)) + z89;
        float c = __fdividef(e, Z);
        u64 cc = pk2(c, c);

        // expand #2 for the accumulate
        expand4(rA.x, t0, t1);
        s[0] = ffma2(t0, cc, s[0]); s[1] = ffma2(t1, cc, s[1]);
        expand4(rA.y, t0, t1);
        s[2] = ffma2(t0, cc, s[2]); s[3] = ffma2(t1, cc, s[3]);
        expand4(rB.x, t0, t1);
        s[4] = ffma2(t0, cc, s[4]); s[5] = ffma2(t1, cc, s[5]);
        expand4(rB.y, t0, t1);
        s[6] = ffma2(t0, cc, s[6]); s[7] = ffma2(t1, cc, s[7]);

        rA = nA; rB = nB;
    }

    // partials into 72-chunk region
    float* sp = g_spart + ((size_t)(chunk*B_TOT + b)*NCAPS + n)*DDIM;
    #pragma unroll
    for (int q = 0; q < 4; q++)
        ((ulonglong2*)sp)[q] = make_ulonglong2(s[2*q], s[2*q+1]);
}

// ---------------- reduce partials + squash (2 warps per (b,n)) ----------------
// NJ=9 -> 36 chunks (pass0), NJ=18 -> 72 chunks (sweeps)
// MODE 0: vc = v ; MODE 1: vc += v ; MODE 2: out = v
template<int MODE, int NJ>
__global__ void k_reduce(float* __restrict__ out, float scale){
    __shared__ float red[4][2][16];
    const int tid  = threadIdx.x;
    const int wid  = tid >> 5;
    const int lane = tid & 31;
    const int pib  = wid >> 1;
    const int half = wid & 1;
    const int pair = blockIdx.x * 4 + pib;     // (b,n) in [0, 2560)
    const int d    = lane & 15;
    const int hh   = lane >> 4;
    const size_t base = (size_t)pair * DDIM + d;

    float s = 0.f;
    #pragma unroll
    for (int j = 0; j < NJ; j++)
        s += g_spart[(size_t)(half*2 + hh + 4*j) * SND + base];
    s += __shfl_xor_sync(0xffffffffu, s, 16);
    if (lane < 16) red[pib][half][d] = s;
    __syncthreads();
    if (half == 0){
        float st = (red[pib][0][d] + red[pib][1][d]) * scale;
        float sq = st * st;
        sq += __shfl_xor_sync(0xffffffffu, sq, 1);
        sq += __shfl_xor_sync(0xffffffffu, sq, 2);
        sq += __shfl_xor_sync(0xffffffffu, sq, 4);
        sq += __shfl_xor_sync(0xffffffffu, sq, 8);
        float nrm = sqrtf(sq);
        float vv = (sq / (1.0f + sq)) * (st / (nrm + 1e-8f));
        if (lane < 16){
            if (MODE == 0)      g_vc[base] = vv;
            else if (MODE == 1) g_vc[base] += vv;
            else                out[base] = vv;
        }
    }
}

// ---------------- launch ----------------
extern "C" void kernel_launch(void* const* d_in, const int* in_sizes, int n_in,
                              void* d_out, int out_size){
    const float* x = (const float*)d_in[0];
    const float* W = (const float*)d_in[1];
    if (n_in >= 2 && in_sizes[0] == WELEMS){   // defensive order swap
        const float* t = x; x = W; W = t;
    }
    float* out = (float*)d_out;

    k_prep<<<XBLKS + WBLKS, 1024>>>(x, W);

    const int RB = (B_TOT*NCAPS)/4;    // 640 blocks

    k_pass0<<<dim3(P0CH, BGROUPS), 320>>>();
    k_reduce<0, 9><<<RB, 256>>>(nullptr, 0.1f);   // c = softmax(0) = 1/10

    dim3 sg(SWCH, BGROUPS);
    k_sweep<<<sg, 320>>>();
    k_reduce<1, 18><<<RB, 256>>>(nullptr, 1.0f);

    k_sweep<<<sg, 320>>>();
    k_reduce<1, 18><<<RB, 256>>>(nullptr, 1.0f);

    k_sweep<<<sg, 320>>>();
    k_reduce<2, 18><<<RB, 256>>>(out, 1.0f);
}

// round 13
// speedup vs baseline: 1.4548x; 1.2934x over previous
#include <cuda_runtime.h>

typedef unsigned long long u64;
typedef unsigned int u32;

#define B_TOT   256
#define IN_CAPS 1152
#define KDIM    8
#define NCAPS   10
#define DDIM    16
#define P0CH    36              /* pass0 i-chunks (32 i each)  */
#define SWCH    36              /* sweep i-chunks (32 i each)  */
#define BGROUPS 8
#define SND     (B_TOT*NCAPS*DDIM)      /* 40960 */
#define FDIM    (IN_CAPS*KDIM)          /* 9216  */
#define XELEMS  (IN_CAPS*B_TOT*KDIM)
#define XBLKS   ((FDIM/32)*(B_TOT/32))  /* 2304  */
#define WELEMS  (NCAPS*IN_CAPS*128)
#define WBLKS   ((WELEMS+1023)/1024)
#define XSTRIDE (B_TOT*KDIM)            /* 2048 floats per i */

// ---------------- scratch (static device memory, no allocs) ----------------
__device__ float g_Wt[NCAPS*IN_CAPS*128];            // W transposed: [n][i][k][d]
__device__ float g_xI[XELEMS];                       // x re-laid:   [i][b][k]
__device__ float g_spart[P0CH*SND];                  // per-chunk partial s
__device__ float g_vc[SND];                          // CUMULATIVE v  [b][n][d]
__device__ u64   g_uh[(size_t)NCAPS*IN_CAPS*B_TOT*4];// u_hat fp16: [n][i][b][dq] (32B per (n,i,b))

// ---------------- f32x2 / pack helpers ----------------
__device__ __forceinline__ u64 pk2(float x, float y){
    u64 r; asm("mov.b64 %0,{%1,%2};" : "=l"(r) : "f"(x), "f"(y)); return r;
}
__device__ __forceinline__ u64 pk2u(u32 x, u32 y){
    u64 r; asm("mov.b64 %0,{%1,%2};" : "=l"(r) : "r"(x), "r"(y)); return r;
}
__device__ __forceinline__ void upk2(u64 a, float& x, float& y){
    asm("mov.b64 {%0,%1},%2;" : "=f"(x), "=f"(y) : "l"(a));
}
__device__ __forceinline__ void upk2u(u64 a, u32& x, u32& y){
    asm("mov.b64 {%0,%1},%2;" : "=r"(x), "=r"(y) : "l"(a));
}
__device__ __forceinline__ u64 ffma2(u64 a, u64 b, u64 c){
    u64 d; asm("fma.rn.f32x2 %0,%1,%2,%3;" : "=l"(d) : "l"(a), "l"(b), "l"(c)); return d;
}
__device__ __forceinline__ u64 fmul2(u64 a, u64 b){
    u64 d; asm("mul.rn.f32x2 %0,%1,%2;" : "=l"(d) : "l"(a), "l"(b)); return d;
}
__device__ __forceinline__ u64 fadd2(u64 a, u64 b){
    u64 d; asm("add.rn.f32x2 %0,%1,%2;" : "=l"(d) : "l"(a), "l"(b)); return d;
}
__device__ __forceinline__ u32 smemu32(const void* p){
    u32 a; asm("{ .reg .u64 t; cvta.to.shared.u64 t, %1; cvt.u32.u64 %0, t; }" : "=r"(a) : "l"(p));
    return a;
}
__device__ __forceinline__ void cpasync16(u32 dst, const void* src){
    asm volatile("cp.async.ca.shared.global [%0],[%1],16;" :: "r"(dst), "l"(src));
}
__device__ __forceinline__ void cpcommit(){ asm volatile("cp.async.commit_group;"); }
__device__ __forceinline__ void cpwait1(){ asm volatile("cp.async.wait_group 1;"); }

// f32x2 pair -> f16x2 (low half = even d, high half = odd d)
__device__ __forceinline__ u32 hfp(u64 p){
    float x, y; upk2(p, x, y);
    u32 r; asm("cvt.rn.f16x2.f32 %0, %1, %2;" : "=r"(r) : "f"(y), "f"(x));
    return r;
}
// f16x2 -> f32x2 (even d in low word)
__device__ __forceinline__ u64 expand_h2(u32 hpair){
    float lo, hi;
    asm("{ .reg .f16 a, b;\n\t"
        "  mov.b32 {a, b}, %2;\n\t"
        "  cvt.f32.f16 %0, a;\n\t"
        "  cvt.f32.f16 %1, b; }"
        : "=f"(lo), "=f"(hi) : "r"(hpair));
    return pk2(lo, hi);
}
// u64 of 4 fp16 -> two f32x2 pairs
__device__ __forceinline__ void expand4(u64 r, u64& p0, u64& p1){
    u32 a, b; upk2u(r, a, b);
    p0 = expand_h2(a);
    p1 = expand_h2(b);
}

// dot of a 32B fp16 row (2x ulonglong2) with v[8], expanding transiently
__device__ __forceinline__ float dot16(ulonglong2 rA, ulonglong2 rB, const u64* v){
    u64 t0, t1;
    expand4(rA.x, t0, t1);
    u64 d0 = fmul2(t0, v[0]); d0 = ffma2(t1, v[1], d0);
    expand4(rA.y, t0, t1);
    d0 = ffma2(t0, v[2], d0); d0 = ffma2(t1, v[3], d0);
    expand4(rB.x, t0, t1);
    d0 = ffma2(t0, v[4], d0); d0 = ffma2(t1, v[5], d0);
    expand4(rB.y, t0, t1);
    d0 = ffma2(t0, v[6], d0); d0 = ffma2(t1, v[7], d0);
    float lo, hi; upk2(d0, lo, hi);
    return lo + hi;
}
// accumulate c * row into s[8]
__device__ __forceinline__ void acc16(ulonglong2 rA, ulonglong2 rB, u64 cc, u64* s){
    u64 t0, t1;
    expand4(rA.x, t0, t1);
    s[0] = ffma2(t0, cc, s[0]); s[1] = ffma2(t1, cc, s[1]);
    expand4(rA.y, t0, t1);
    s[2] = ffma2(t0, cc, s[2]); s[3] = ffma2(t1, cc, s[3]);
    expand4(rB.x, t0, t1);
    s[4] = ffma2(t0, cc, s[4]); s[5] = ffma2(t1, cc, s[5]);
    expand4(rB.y, t0, t1);
    s[6] = ffma2(t0, cc, s[6]); s[7] = ffma2(t1, cc, s[7]);
}

// half-warp tu: this thread's d-half (hb = h*2) for TWO batches, sharing W loads.
__device__ __forceinline__ void tu_half2(const ulonglong2* __restrict__ wr, int hb,
                                         const float* __restrict__ XL,
                                         const float* __restrict__ XH,
                                         u64* aL, u64* aH){
    #pragma unroll
    for (int k = 0; k < 8; k++){
        u64 xkL = pk2(XL[k], XL[k]);
        u64 xkH = pk2(XH[k], XH[k]);
        ulonglong2 w0 = wr[k*4 + hb];
        ulonglong2 w1 = wr[k*4 + hb + 1];
        if (k == 0){
            aL[0] = fmul2(w0.x, xkL); aL[1] = fmul2(w0.y, xkL);
            aL[2] = fmul2(w1.x, xkL); aL[3] = fmul2(w1.y, xkL);
            aH[0] = fmul2(w0.x, xkH); aH[1] = fmul2(w0.y, xkH);
            aH[2] = fmul2(w1.x, xkH); aH[3] = fmul2(w1.y, xkH);
        } else {
            aL[0] = ffma2(w0.x, xkL, aL[0]); aL[1] = ffma2(w0.y, xkL, aL[1]);
            aL[2] = ffma2(w1.x, xkL, aL[2]); aL[3] = ffma2(w1.y, xkL, aL[3]);
            aH[0] = ffma2(w0.x, xkH, aH[0]); aH[1] = ffma2(w0.y, xkH, aH[1]);
            aH[2] = ffma2(w1.x, xkH, aH[2]); aH[3] = ffma2(w1.y, xkH, aH[3]);
        }
    }
}

// ---------------- prep: x re-layout (coalesced) + W transpose ----------------
__global__ void k_prep(const float* __restrict__ x, const float* __restrict__ W){
    __shared__ float t[32][33];
    int xb = blockIdx.x;
    int tid = threadIdx.x;
    if (xb < XBLKS){
        int f0 = (xb % (FDIM/32)) * 32;
        int b0 = (xb / (FDIM/32)) * 32;
        int b_loc = tid >> 5, f_loc = tid & 31;
        t[b_loc][f_loc] = x[(size_t)(b0 + b_loc) * FDIM + f0 + f_loc];
        __syncthreads();
        int i_loc = tid >> 8;
        int r = tid & 255;
        int b = r >> 3, k = r & 7;
        g_xI[(size_t)(f0/8 + i_loc) * XSTRIDE + (b0 + b) * KDIM + k] = t[b][i_loc*8 + k];
    } else {
        int idx = (xb - XBLKS) * 1024 + tid;
        if (idx < WELEMS){
            int k  = idx & 7;
            int d  = (idx >> 3) & 15;
            int ni = idx >> 7;
            g_Wt[(ni << 7) | (k << 4) | d] = W[idx];
        }
    }
}

// ---------------- pass0: compute u_hat (fp32), accumulate s0, store u_hat fp16 ----
// warp = capsule n, half-warp d-split, 2 batches/thread. grid (36, 8), 2 CTAs/SM.
__global__ void __launch_bounds__(320, 2) k_pass0(){
    __shared__ __align__(16) float ws[2][NCAPS*128];

    const int tid   = threadIdx.x;
    const int n     = tid >> 5;
    const int lane  = tid & 31;
    const int l16   = lane & 15;
    const int h     = lane >> 4;
    const int hb    = h * 2;
    const int chunk = blockIdx.x;
    const int bg    = blockIdx.y;
    const int i0    = chunk * 32;
    const int b_lo  = bg * 32 + l16;
    const int b_hi  = b_lo + 16;

    u64 sL[4], sH[4];
    #pragma unroll
    for (int p = 0; p < 4; p++){ sL[p] = 0ull; sH[p] = 0ull; }

    const float* wsrc = g_Wt + ((size_t)(n*IN_CAPS + i0))*128 + lane*4;
    const u32 wdst0 = smemu32(&ws[0][n*128 + lane*4]);
    const u32 wdst1 = smemu32(&ws[1][n*128 + lane*4]);
    const float* xl = g_xI + (size_t)i0 * XSTRIDE + b_lo * KDIM;
    const float* xh = g_xI + (size_t)i0 * XSTRIDE + b_hi * KDIM;
    // u_hat [n][i][b][dq]; this thread writes dq = {2h, 2h+1} for b_lo and b_hi
    u64* ub = g_uh + ((size_t)(n*IN_CAPS + i0) * B_TOT + b_lo) * 4 + 2*h;

    cpasync16(wdst0, wsrc); cpcommit();
    #pragma unroll 1
    for (int ii = 0; ii < 32; ii++){
        if (ii + 1 < 32) cpasync16((ii & 1) ? wdst0 : wdst1, wsrc + 128);
        cpcommit();
        wsrc += 128;
        cpwait1();
        float4 q0 = *(const float4*)xl, q1 = *(const float4*)(xl + 4);
        float4 r0 = *(const float4*)xh, r1 = *(const float4*)(xh + 4);
        xl += XSTRIDE; xh += XSTRIDE;
        float XL[8] = {q0.x,q0.y,q0.z,q0.w, q1.x,q1.y,q1.z,q1.w};
        float XH[8] = {r0.x,r0.y,r0.z,r0.w, r1.x,r1.y,r1.z,r1.w};
        u64 aL[4], aH[4];
        tu_half2((const ulonglong2*)&ws[ii & 1][n*128], hb, XL, XH, aL, aH);
        #pragma unroll
        for (int p = 0; p < 4; p++){ sL[p] = fadd2(sL[p], aL[p]); sH[p] = fadd2(sH[p], aH[p]); }
        // fp16 stores: one STG.128 per batch (dq pair contiguous)
        ((ulonglong2*)ub)[0]        = make_ulonglong2(pk2u(hfp(aL[0]), hfp(aL[1])),
                                                      pk2u(hfp(aL[2]), hfp(aL[3])));
        ((ulonglong2*)(ub + 64))[0] = make_ulonglong2(pk2u(hfp(aH[0]), hfp(aH[1])),
                                                      pk2u(hfp(aH[2]), hfp(aH[3])));
        ub += (size_t)B_TOT * 4;
    }

    float* spL = g_spart + ((size_t)(chunk*B_TOT + b_lo)*NCAPS + n)*DDIM + 8*h;
    float* spH = g_spart + ((size_t)(chunk*B_TOT + b_hi)*NCAPS + n)*DDIM + 8*h;
    ((ulonglong2*)spL)[0] = make_ulonglong2(sL[0], sL[1]);
    ((ulonglong2*)spL)[1] = make_ulonglong2(sL[2], sL[3]);
    ((ulonglong2*)spH)[0] = make_ulonglong2(sH[0], sH[1]);
    ((ulonglong2*)spH)[1] = make_ulonglong2(sH[2], sH[3]);
}

// ---------------- routed sweep: stream fp16 u_hat, softmax, accumulate ----------
// warp = capsule n, lane = batch. grid (36, 8) = 288 CTAs, 2 CTAs/SM (1 wave).
// TWO i-steps per barrier pair; next pair's 4 LDG.128 issued before processing
// the current pair (4 loads/thread in flight -> DRAM saturation). Softmax 1/Z
// computed once by reducer warps 0/1.
__global__ void __launch_bounds__(320, 2) k_sweep(){
    __shared__ float ex[4][NCAPS][32];
    __shared__ float zi[4][32];

    const int tid   = threadIdx.x;
    const int n     = tid >> 5;
    const int lane  = tid & 31;
    const int chunk = blockIdx.x;
    const int bg    = blockIdx.y;
    const int i0    = chunk * 32;
    const int b     = bg * 32 + lane;

    u64 v[8];
    {
        const u64* vp = (const u64*)&g_vc[(b*NCAPS + n)*DDIM];
        #pragma unroll
        for (int p = 0; p < 8; p++) v[p] = vp[p];
    }
    u64 s[8];
    #pragma unroll
    for (int p = 0; p < 8; p++) s[p] = 0ull;

    const ulonglong2* up =
        (const ulonglong2*)(g_uh + ((size_t)(n*IN_CAPS + i0) * B_TOT + b) * 4);
    const size_t ISTEP = (size_t)B_TOT * 2;          // one i in ulonglong2 units

    // pair 0 (i0, i0+1)
    ulonglong2 rA0 = up[0],         rB0 = up[1];
    ulonglong2 rA1 = up[ISTEP],     rB1 = up[ISTEP + 1];
    up += 2 * ISTEP;

    #pragma unroll 1
    for (int ii = 0; ii < 32; ii += 2){
        const int bufA = ((ii >> 1) & 1) * 2;

        // prefetch NEXT pair (4 LDG.128 in flight while this pair computes)
        ulonglong2 nA0, nB0, nA1, nB1;
        if (ii + 2 < 32){
            nA0 = up[0];         nB0 = up[1];
            nA1 = up[ISTEP];     nB1 = up[ISTEP + 1];
            up += 2 * ISTEP;
        }

        float eA = __expf(dot16(rA0, rB0, v));   // |logit| small: no max-sub
        float eB = __expf(dot16(rA1, rB1, v));
        ex[bufA][n][lane]     = eA;
        ex[bufA + 1][n][lane] = eB;
        __syncthreads();                          // all e's visible

        if (n < 2){                               // reducer warps: one 1/Z per batch
            const int buf = bufA + n;
            float z01 = ex[buf][0][lane] + ex[buf][1][lane];
            float z23 = ex[buf][2][lane] + ex[buf][3][lane];
            float z45 = ex[buf][4][lane] + ex[buf][5][lane];
            float z67 = ex[buf][6][lane] + ex[buf][7][lane];
            float z89 = ex[buf][8][lane] + ex[buf][9][lane];
            zi[buf][lane] = __fdividef(1.0f, ((z01 + z23) + (z45 + z67)) + z89);
        }
        __syncthreads();                          // invZ visible

        float cA = eA * zi[bufA][lane];
        float cB = eB * zi[bufA + 1][lane];
        u64 ccA = pk2(cA, cA), ccB = pk2(cB, cB);
        acc16(rA0, rB0, ccA, s);
        acc16(rA1, rB1, ccB, s);

        rA0 = nA0; rB0 = nB0; rA1 = nA1; rB1 = nB1;
    }

    float* sp = g_spart + ((size_t)(chunk*B_TOT + b)*NCAPS + n)*DDIM;
    #pragma unroll
    for (int q = 0; q < 4; q++)
        ((ulonglong2*)sp)[q] = make_ulonglong2(s[2*q], s[2*q+1]);
}

// ---------------- reduce partials + squash (2 warps per (b,n), 36 chunks) ------
// MODE 0: vc = v ; MODE 1: vc += v ; MODE 2: out = v
template<int MODE>
__global__ void k_reduce(float* __restrict__ out, float scale){
    __shared__ float red[4][2][16];
    const int tid  = threadIdx.x;
    const int wid  = tid >> 5;
    const int lane = tid & 31;
    const int pib  = wid >> 1;
    const int half = wid & 1;
    const int pair = blockIdx.x * 4 + pib;     // (b,n) in [0, 2560)
    const int d    = lane & 15;
    const int hh   = lane >> 4;
    const size_t base = (size_t)pair * DDIM + d;

    float s = 0.f;
    #pragma unroll
    for (int j = 0; j < 9; j++)
        s += g_spart[(size_t)(half*2 + hh + 4*j) * SND + base];
    s += __shfl_xor_sync(0xffffffffu, s, 16);
    if (lane < 16) red[pib][half][d] = s;
    __syncthreads();
    if (half == 0){
        float st = (red[pib][0][d] + red[pib][1][d]) * scale;
        float sq = st * st;
        sq += __shfl_xor_sync(0xffffffffu, sq, 1);
        sq += __shfl_xor_sync(0xffffffffu, sq, 2);
        sq += __shfl_xor_sync(0xffffffffu, sq, 4);
        sq += __shfl_xor_sync(0xffffffffu, sq, 8);
        float nrm = sqrtf(sq);
        float vv = (sq / (1.0f + sq)) * (st / (nrm + 1e-8f));
        if (lane < 16){
            if (MODE == 0)      g_vc[base] = vv;
            else if (MODE == 1) g_vc[base] += vv;
            else                out[base] = vv;
        }
    }
}

// ---------------- launch ----------------
extern "C" void kernel_launch(void* const* d_in, const int* in_sizes, int n_in,
                              void* d_out, int out_size){
    const float* x = (const float*)d_in[0];
    const float* W = (const float*)d_in[1];
    if (n_in >= 2 && in_sizes[0] == WELEMS){   // defensive order swap
        const float* t = x; x = W; W = t;
    }
    float* out = (float*)d_out;

    k_prep<<<XBLKS + WBLKS, 1024>>>(x, W);

    const int RB = (B_TOT*NCAPS)/4;    // 640 blocks

    k_pass0<<<dim3(P0CH, BGROUPS), 320>>>();
    k_reduce<0><<<RB, 256>>>(nullptr, 0.1f);   // c = softmax(0) = 1/10

    dim3 sg(SWCH, BGROUPS);
    k_sweep<<<sg, 320>>>();
    k_reduce<1><<<RB, 256>>>(nullptr, 1.0f);

    k_sweep<<<sg, 320>>>();
    k_reduce<1><<<RB, 256>>>(nullptr, 1.0f);

    k_sweep<<<sg, 320>>>();
    k_reduce<2><<<RB, 256>>>(out, 1.0f);
}

// round 14
// speedup vs baseline: 1.4673x; 1.0085x over previous
#include <cuda_runtime.h>

typedef unsigned long long u64;
typedef unsigned int u32;

#define B_TOT   256
#define IN_CAPS 1152
#define KDIM    8
#define NCAPS   10
#define DDIM    16
#define P0CH    36              /* pass0 i-chunks (32 i each)  */
#define SWCH    36              /* sweep i-chunks (32 i each)  */
#define BGROUPS 8
#define SND     (B_TOT*NCAPS*DDIM)      /* 40960 */
#define FDIM    (IN_CAPS*KDIM)          /* 9216  */
#define XELEMS  (IN_CAPS*B_TOT*KDIM)
#define XBLKS   ((FDIM/32)*(B_TOT/32))  /* 2304  */
#define WELEMS  (NCAPS*IN_CAPS*128)
#define WBLKS   ((WELEMS+1023)/1024)
#define XSTRIDE (B_TOT*KDIM)            /* 2048 floats per i */

// ---------------- scratch (static device memory, no allocs) ----------------
__device__ float g_Wt[NCAPS*IN_CAPS*128];            // W transposed: [n][i][k][d]
__device__ float g_xI[XELEMS];                       // x re-laid:   [i][b][k]
__device__ float g_spart[P0CH*SND];                  // per-chunk partial s
__device__ float g_vc[SND];                          // CUMULATIVE v  [b][n][d]
__device__ u64   g_uh[(size_t)NCAPS*IN_CAPS*B_TOT*4];// u_hat fp16: [n][i][b][dq] (32B per (n,i,b))

// ---------------- f32x2 / pack helpers ----------------
__device__ __forceinline__ u64 pk2(float x, float y){
    u64 r; asm("mov.b64 %0,{%1,%2};" : "=l"(r) : "f"(x), "f"(y)); return r;
}
__device__ __forceinline__ u64 pk2u(u32 x, u32 y){
    u64 r; asm("mov.b64 %0,{%1,%2};" : "=l"(r) : "r"(x), "r"(y)); return r;
}
__device__ __forceinline__ void upk2(u64 a, float& x, float& y){
    asm("mov.b64 {%0,%1},%2;" : "=f"(x), "=f"(y) : "l"(a));
}
__device__ __forceinline__ void upk2u(u64 a, u32& x, u32& y){
    asm("mov.b64 {%0,%1},%2;" : "=r"(x), "=r"(y) : "l"(a));
}
__device__ __forceinline__ u64 ffma2(u64 a, u64 b, u64 c){
    u64 d; asm("fma.rn.f32x2 %0,%1,%2,%3;" : "=l"(d) : "l"(a), "l"(b), "l"(c)); return d;
}
__device__ __forceinline__ u64 fmul2(u64 a, u64 b){
    u64 d; asm("mul.rn.f32x2 %0,%1,%2;" : "=l"(d) : "l"(a), "l"(b)); return d;
}
__device__ __forceinline__ u64 fadd2(u64 a, u64 b){
    u64 d; asm("add.rn.f32x2 %0,%1,%2;" : "=l"(d) : "l"(a), "l"(b)); return d;
}
__device__ __forceinline__ u32 smemu32(const void* p){
    u32 a; asm("{ .reg .u64 t; cvta.to.shared.u64 t, %1; cvt.u32.u64 %0, t; }" : "=r"(a) : "l"(p));
    return a;
}
__device__ __forceinline__ void cpasync16(u32 dst, const void* src){
    asm volatile("cp.async.ca.shared.global [%0],[%1],16;" :: "r"(dst), "l"(src));
}
__device__ __forceinline__ void cpcommit(){ asm volatile("cp.async.commit_group;"); }
__device__ __forceinline__ void cpwait1(){ asm volatile("cp.async.wait_group 1;"); }

// f32x2 pair -> f16x2 (low half = even d, high half = odd d)
__device__ __forceinline__ u32 hfp(u64 p){
    float x, y; upk2(p, x, y);
    u32 r; asm("cvt.rn.f16x2.f32 %0, %1, %2;" : "=r"(r) : "f"(y), "f"(x));
    return r;
}
// f16x2 -> f32x2 (even d in low word)
__device__ __forceinline__ u64 expand_h2(u32 hpair){
    float lo, hi;
    asm("{ .reg .f16 a, b;\n\t"
        "  mov.b32 {a, b}, %2;\n\t"
        "  cvt.f32.f16 %0, a;\n\t"
        "  cvt.f32.f16 %1, b; }"
        : "=f"(lo), "=f"(hi) : "r"(hpair));
    return pk2(lo, hi);
}
// u64 of 4 fp16 -> two f32x2 pairs
__device__ __forceinline__ void expand4(u64 r, u64& p0, u64& p1){
    u32 a, b; upk2u(r, a, b);
    p0 = expand_h2(a);
    p1 = expand_h2(b);
}

// half-warp tu: this thread's d-half (hb = h*2) for TWO batches, sharing W loads.
__device__ __forceinline__ void tu_half2(const ulonglong2* __restrict__ wr, int hb,
                                         const float* __restrict__ XL,
                                         const float* __restrict__ XH,
                                         u64* aL, u64* aH){
    #pragma unroll
    for (int k = 0; k < 8; k++){
        u64 xkL = pk2(XL[k], XL[k]);
        u64 xkH = pk2(XH[k], XH[k]);
        ulonglong2 w0 = wr[k*4 + hb];
        ulonglong2 w1 = wr[k*4 + hb + 1];
        if (k == 0){
            aL[0] = fmul2(w0.x, xkL); aL[1] = fmul2(w0.y, xkL);
            aL[2] = fmul2(w1.x, xkL); aL[3] = fmul2(w1.y, xkL);
            aH[0] = fmul2(w0.x, xkH); aH[1] = fmul2(w0.y, xkH);
            aH[2] = fmul2(w1.x, xkH); aH[3] = fmul2(w1.y, xkH);
        } else {
            aL[0] = ffma2(w0.x, xkL, aL[0]); aL[1] = ffma2(w0.y, xkL, aL[1]);
            aL[2] = ffma2(w1.x, xkL, aL[2]); aL[3] = ffma2(w1.y, xkL, aL[3]);
            aH[0] = ffma2(w0.x, xkH, aH[0]); aH[1] = ffma2(w0.y, xkH, aH[1]);
            aH[2] = ffma2(w1.x, xkH, aH[2]); aH[3] = ffma2(w1.y, xkH, aH[3]);
        }
    }
}

// ---------------- prep: x re-layout (coalesced) + W transpose ----------------
__global__ void k_prep(const float* __restrict__ x, const float* __restrict__ W){
    __shared__ float t[32][33];
    int xb = blockIdx.x;
    int tid = threadIdx.x;
    if (xb < XBLKS){
        int f0 = (xb % (FDIM/32)) * 32;
        int b0 = (xb / (FDIM/32)) * 32;
        int b_loc = tid >> 5, f_loc = tid & 31;
        t[b_loc][f_loc] = x[(size_t)(b0 + b_loc) * FDIM + f0 + f_loc];
        __syncthreads();
        int i_loc = tid >> 8;
        int r = tid & 255;
        int b = r >> 3, k = r & 7;
        g_xI[(size_t)(f0/8 + i_loc) * XSTRIDE + (b0 + b) * KDIM + k] = t[b][i_loc*8 + k];
    } else {
        int idx = (xb - XBLKS) * 1024 + tid;
        if (idx < WELEMS){
            int k  = idx & 7;
            int d  = (idx >> 3) & 15;
            int ni = idx >> 7;
            g_Wt[(ni << 7) | (k << 4) | d] = W[idx];
        }
    }
}

// ---------------- pass0: compute u_hat (fp32), accumulate s0, store u_hat fp16 ----
// warp = capsule n, half-warp d-split, 2 batches/thread. grid (36, 8), 2 CTAs/SM.
__global__ void __launch_bounds__(320, 2) k_pass0(){
    __shared__ __align__(16) float ws[2][NCAPS*128];

    const int tid   = threadIdx.x;
    const int n     = tid >> 5;
    const int lane  = tid & 31;
    const int l16   = lane & 15;
    const int h     = lane >> 4;
    const int hb    = h * 2;
    const int chunk = blockIdx.x;
    const int bg    = blockIdx.y;
    const int i0    = chunk * 32;
    const int b_lo  = bg * 32 + l16;
    const int b_hi  = b_lo + 16;

    u64 sL[4], sH[4];
    #pragma unroll
    for (int p = 0; p < 4; p++){ sL[p] = 0ull; sH[p] = 0ull; }

    const float* wsrc = g_Wt + ((size_t)(n*IN_CAPS + i0))*128 + lane*4;
    const u32 wdst0 = smemu32(&ws[0][n*128 + lane*4]);
    const u32 wdst1 = smemu32(&ws[1][n*128 + lane*4]);
    const float* xl = g_xI + (size_t)i0 * XSTRIDE + b_lo * KDIM;
    const float* xh = g_xI + (size_t)i0 * XSTRIDE + b_hi * KDIM;
    // u_hat [n][i][b][dq]; this thread writes dq = {2h, 2h+1} for b_lo and b_hi
    u64* ub = g_uh + ((size_t)(n*IN_CAPS + i0) * B_TOT + b_lo) * 4 + 2*h;

    cpasync16(wdst0, wsrc); cpcommit();
    #pragma unroll 1
    for (int ii = 0; ii < 32; ii++){
        if (ii + 1 < 32) cpasync16((ii & 1) ? wdst0 : wdst1, wsrc + 128);
        cpcommit();
        wsrc += 128;
        cpwait1();
        float4 q0 = *(const float4*)xl, q1 = *(const float4*)(xl + 4);
        float4 r0 = *(const float4*)xh, r1 = *(const float4*)(xh + 4);
        xl += XSTRIDE; xh += XSTRIDE;
        float XL[8] = {q0.x,q0.y,q0.z,q0.w, q1.x,q1.y,q1.z,q1.w};
        float XH[8] = {r0.x,r0.y,r0.z,r0.w, r1.x,r1.y,r1.z,r1.w};
        u64 aL[4], aH[4];
        tu_half2((const ulonglong2*)&ws[ii & 1][n*128], hb, XL, XH, aL, aH);
        #pragma unroll
        for (int p = 0; p < 4; p++){ sL[p] = fadd2(sL[p], aL[p]); sH[p] = fadd2(sH[p], aH[p]); }
        // fp16 stores: one STG.128 per batch (dq pair contiguous)
        ((ulonglong2*)ub)[0]        = make_ulonglong2(pk2u(hfp(aL[0]), hfp(aL[1])),
                                                      pk2u(hfp(aL[2]), hfp(aL[3])));
        ((ulonglong2*)(ub + 64))[0] = make_ulonglong2(pk2u(hfp(aH[0]), hfp(aH[1])),
                                                      pk2u(hfp(aH[2]), hfp(aH[3])));
        ub += (size_t)B_TOT * 4;
    }

    float* spL = g_spart + ((size_t)(chunk*B_TOT + b_lo)*NCAPS + n)*DDIM + 8*h;
    float* spH = g_spart + ((size_t)(chunk*B_TOT + b_hi)*NCAPS + n)*DDIM + 8*h;
    ((ulonglong2*)spL)[0] = make_ulonglong2(sL[0], sL[1]);
    ((ulonglong2*)spL)[1] = make_ulonglong2(sL[2], sL[3]);
    ((ulonglong2*)spH)[0] = make_ulonglong2(sH[0], sH[1]);
    ((ulonglong2*)spH)[1] = make_ulonglong2(sH[2], sH[3]);
}

// ---------------- routed sweep: stream fp16 u_hat, softmax, accumulate ----------
// warp = capsule n, lane = batch. grid (36, 8) = 288 CTAs, 2 CTAs/SM (1 wave).
// TWO i-steps per barrier pair. Rows are expanded fp16->f32x2 ONCE per pair; the
// next pair's 4 LDG.128 are issued into the raw registers immediately after the
// expand (WAR dependence = no extra prefetch registers, no ptxas hoisting).
__global__ void __launch_bounds__(320, 2) k_sweep(){
    __shared__ float ex[4][NCAPS][32];
    __shared__ float zi[4][32];

    const int tid   = threadIdx.x;
    const int n     = tid >> 5;
    const int lane  = tid & 31;
    const int chunk = blockIdx.x;
    const int bg    = blockIdx.y;
    const int i0    = chunk * 32;
    const int b     = bg * 32 + lane;

    u64 v[8];
    {
        const u64* vp = (const u64*)&g_vc[(b*NCAPS + n)*DDIM];
        #pragma unroll
        for (int p = 0; p < 8; p++) v[p] = vp[p];
    }
    u64 s[8];
    #pragma unroll
    for (int p = 0; p < 8; p++) s[p] = 0ull;

    const ulonglong2* up =
        (const ulonglong2*)(g_uh + ((size_t)(n*IN_CAPS + i0) * B_TOT + b) * 4);
    const size_t ISTEP = (size_t)B_TOT * 2;          // one i in ulonglong2 units

    // raw fp16 rows for the current pair (i0, i0+1)
    ulonglong2 rA0 = up[0],         rB0 = up[1];
    ulonglong2 rA1 = up[ISTEP],     rB1 = up[ISTEP + 1];
    up += 2 * ISTEP;

    #pragma unroll 1
    for (int ii = 0; ii < 32; ii += 2){
        const int bufA = ((ii >> 1) & 1) * 2;

        // expand current pair ONCE (raw regs become dead after this)
        u64 E0[8], E1[8];
        expand4(rA0.x, E0[0], E0[1]); expand4(rA0.y, E0[2], E0[3]);
        expand4(rB0.x, E0[4], E0[5]); expand4(rB0.y, E0[6], E0[7]);
        expand4(rA1.x, E1[0], E1[1]); expand4(rA1.y, E1[2], E1[3]);
        expand4(rB1.x, E1[4], E1[5]); expand4(rB1.y, E1[6], E1[7]);

        // issue next pair's loads into the freed raw regs (covered by the
        // dot/exchange/acc phase below)
        if (ii + 2 < 32){
            rA0 = up[0];         rB0 = up[1];
            rA1 = up[ISTEP];     rB1 = up[ISTEP + 1];
            up += 2 * ISTEP;
        }

        // dots from the expanded copies
        u64 dA = fmul2(E0[0], v[0]);
        u64 dB = fmul2(E1[0], v[0]);
        #pragma unroll
        for (int p = 1; p < 8; p++){
            dA = ffma2(E0[p], v[p], dA);
            dB = ffma2(E1[p], v[p], dB);
        }
        float lo, hi, fA, fB;
        upk2(dA, lo, hi); fA = lo + hi;
        upk2(dB, lo, hi); fB = lo + hi;
        float eA = __expf(fA), eB = __expf(fB);   // |logit| small: no max-sub
        ex[bufA][n][lane]     = eA;
        ex[bufA + 1][n][lane] = eB;
        __syncthreads();                          // all e's visible

        if (n < 2){                               // reducer warps: one 1/Z per batch
            const int buf = bufA + n;
            float z01 = ex[buf][0][lane] + ex[buf][1][lane];
            float z23 = ex[buf][2][lane] + ex[buf][3][lane];
            float z45 = ex[buf][4][lane] + ex[buf][5][lane];
            float z67 = ex[buf][6][lane] + ex[buf][7][lane];
            float z89 = ex[buf][8][lane] + ex[buf][9][lane];
            zi[buf][lane] = __fdividef(1.0f, ((z01 + z23) + (z45 + z67)) + z89);
        }
        __syncthreads();                          // invZ visible

        float cA = eA * zi[bufA][lane];
        float cB = eB * zi[bufA + 1][lane];
        u64 ccA = pk2(cA, cA), ccB = pk2(cB, cB);
        #pragma unroll
        for (int p = 0; p < 8; p++){
            s[p] = ffma2(E0[p], ccA, s[p]);
            s[p] = ffma2(E1[p], ccB, s[p]);
        }
    }

    float* sp = g_spart + ((size_t)(chunk*B_TOT + b)*NCAPS + n)*DDIM;
    #pragma unroll
    for (int q = 0; q < 4; q++)
        ((ulonglong2*)sp)[q] = make_ulonglong2(s[2*q], s[2*q+1]);
}

// ---------------- reduce partials + squash (2 warps per (b,n), 36 chunks) ------
// MODE 0: vc = v ; MODE 1: vc += v ; MODE 2: out = v
template<int MODE>
__global__ void k_reduce(float* __restrict__ out, float scale){
    __shared__ float red[4][2][16];
    const int tid  = threadIdx.x;
    const int wid  = tid >> 5;
    const int lane = tid & 31;
    const int pib  = wid >> 1;
    const int half = wid & 1;
    const int pair = blockIdx.x * 4 + pib;     // (b,n) in [0, 2560)
    const int d    = lane & 15;
    const int hh   = lane >> 4;
    const size_t base = (size_t)pair * DDIM + d;

    float s = 0.f;
    #pragma unroll
    for (int j = 0; j < 9; j++)
        s += g_spart[(size_t)(half*2 + hh + 4*j) * SND + base];
    s += __shfl_xor_sync(0xffffffffu, s, 16);
    if (lane < 16) red[pib][half][d] = s;
    __syncthreads();
    if (half == 0){
        float st = (red[pib][0][d] + red[pib][1][d]) * scale;
        float sq = st * st;
        sq += __shfl_xor_sync(0xffffffffu, sq, 1);
        sq += __shfl_xor_sync(0xffffffffu, sq, 2);
        sq += __shfl_xor_sync(0xffffffffu, sq, 4);
        sq += __shfl_xor_sync(0xffffffffu, sq, 8);
        float nrm = sqrtf(sq);
        float vv = (sq / (1.0f + sq)) * (st / (nrm + 1e-8f));
        if (lane < 16){
            if (MODE == 0)      g_vc[base] = vv;
            else if (MODE == 1) g_vc[base] += vv;
            else                out[base] = vv;
        }
    }
}

// ---------------- launch ----------------
extern "C" void kernel_launch(void* const* d_in, const int* in_sizes, int n_in,
                              void* d_out, int out_size){
    const float* x = (const float*)d_in[0];
    const float* W = (const float*)d_in[1];
    if (n_in >= 2 && in_sizes[0] == WELEMS){   // defensive order swap
        const float* t = x; x = W; W = t;
    }
    float* out = (float*)d_out;

    k_prep<<<XBLKS + WBLKS, 1024>>>(x, W);

    const int RB = (B_TOT*NCAPS)/4;    // 640 blocks

    k_pass0<<<dim3(P0CH, BGROUPS), 320>>>();
    k_reduce<0><<<RB, 256>>>(nullptr, 0.1f);   // c = softmax(0) = 1/10

    dim3 sg(SWCH, BGROUPS);
    k_sweep<<<sg, 320>>>();
    k_reduce<1><<<RB, 256>>>(nullptr, 1.0f);

    k_sweep<<<sg, 320>>>();
    k_reduce<1><<<RB, 256>>>(nullptr, 1.0f);

    k_sweep<<<sg, 320>>>();
    k_reduce<2><<<RB, 256>>>(out, 1.0f);
}

// round 16
// speedup vs baseline: 1.4920x; 1.0168x over previous
#include <cuda_runtime.h>

typedef unsigned long long u64;
typedef unsigned int u32;

#define B_TOT   256
#define IN_CAPS 1152
#define KDIM    8
#define NCAPS   10
#define DDIM    16
#define P0CH    36              /* pass0 i-chunks (32 i each)  */
#define SWCH    36              /* sweep i-chunks (32 i each)  */
#define BGROUPS 8
#define SND     (B_TOT*NCAPS*DDIM)      /* 40960 */
#define FDIM    (IN_CAPS*KDIM)          /* 9216  */
#define XELEMS  (IN_CAPS*B_TOT*KDIM)
#define XBLKS   ((FDIM/32)*(B_TOT/32))  /* 2304  */
#define WELEMS  (NCAPS*IN_CAPS*128)
#define WBLKS   ((WELEMS+1023)/1024)
#define XSTRIDE (B_TOT*KDIM)            /* 2048 floats per i */

// ---------------- scratch (static device memory, no allocs) ----------------
__device__ float g_Wt[NCAPS*IN_CAPS*128];            // W transposed: [n][i][k][d]
__device__ float g_xI[XELEMS];                       // x re-laid:   [i][b][k]
__device__ float g_spart[P0CH*SND];                  // per-chunk partial s
__device__ float g_vc[SND];                          // CUMULATIVE v  [b][n][d]
__device__ __align__(32) u64 g_uh[(size_t)NCAPS*IN_CAPS*B_TOT*4]; // u_hat fp16: [n][i][b][dq]

// ---------------- f32x2 / pack helpers ----------------
__device__ __forceinline__ u64 pk2(float x, float y){
    u64 r; asm("mov.b64 %0,{%1,%2};" : "=l"(r) : "f"(x), "f"(y)); return r;
}
__device__ __forceinline__ u64 pk2u(u32 x, u32 y){
    u64 r; asm("mov.b64 %0,{%1,%2};" : "=l"(r) : "r"(x), "r"(y)); return r;
}
__device__ __forceinline__ void upk2(u64 a, float& x, float& y){
    asm("mov.b64 {%0,%1},%2;" : "=f"(x), "=f"(y) : "l"(a));
}
__device__ __forceinline__ void upk2u(u64 a, u32& x, u32& y){
    asm("mov.b64 {%0,%1},%2;" : "=r"(x), "=r"(y) : "l"(a));
}
__device__ __forceinline__ u64 ffma2(u64 a, u64 b, u64 c){
    u64 d; asm("fma.rn.f32x2 %0,%1,%2,%3;" : "=l"(d) : "l"(a), "l"(b), "l"(c)); return d;
}
__device__ __forceinline__ u64 fmul2(u64 a, u64 b){
    u64 d; asm("mul.rn.f32x2 %0,%1,%2;" : "=l"(d) : "l"(a), "l"(b)); return d;
}
__device__ __forceinline__ u64 fadd2(u64 a, u64 b){
    u64 d; asm("add.rn.f32x2 %0,%1,%2;" : "=l"(d) : "l"(a), "l"(b)); return d;
}
__device__ __forceinline__ u32 smemu32(const void* p){
    u32 a; asm("{ .reg .u64 t; cvta.to.shared.u64 t, %1; cvt.u32.u64 %0, t; }" : "=r"(a) : "l"(p));
    return a;
}
__device__ __forceinline__ void cpasync16(u32 dst, const void* src){
    asm volatile("cp.async.ca.shared.global [%0],[%1],16;" :: "r"(dst), "l"(src));
}
__device__ __forceinline__ void cpcommit(){ asm volatile("cp.async.commit_group;"); }
__device__ __forceinline__ void cpwait1(){ asm volatile("cp.async.wait_group 1;"); }

// 256-bit L2::evict_last global accesses (sm_103a requires .v4.b64 for the hint).
// One access = one full 32B u_hat row for (n, i, b).
__device__ __forceinline__ ulonglong4 ldg_el(const u64* p){
    ulonglong4 r;
    asm volatile("ld.global.L2::evict_last.v4.b64 {%0,%1,%2,%3}, [%4];"
                 : "=l"(r.x), "=l"(r.y), "=l"(r.z), "=l"(r.w) : "l"(p));
    return r;
}
__device__ __forceinline__ void stg_el(u64* p, u64 a, u64 b, u64 c, u64 d){
    asm volatile("st.global.L2::evict_last.v4.b64 [%0], {%1,%2,%3,%4};"
                 :: "l"(p), "l"(a), "l"(b), "l"(c), "l"(d) : "memory");
}

// f32x2 pair -> f16x2 (low half = even d, high half = odd d)
__device__ __forceinline__ u32 hfp(u64 p){
    float x, y; upk2(p, x, y);
    u32 r; asm("cvt.rn.f16x2.f32 %0, %1, %2;" : "=r"(r) : "f"(y), "f"(x));
    return r;
}
// f16x2 -> f32x2 (even d in low word)
__device__ __forceinline__ u64 expand_h2(u32 hpair){
    float lo, hi;
    asm("{ .reg .f16 a, b;\n\t"
        "  mov.b32 {a, b}, %2;\n\t"
        "  cvt.f32.f16 %0, a;\n\t"
        "  cvt.f32.f16 %1, b; }"
        : "=f"(lo), "=f"(hi) : "r"(hpair));
    return pk2(lo, hi);
}
// u64 of 4 fp16 -> two f32x2 pairs
__device__ __forceinline__ void expand4(u64 r, u64& p0, u64& p1){
    u32 a, b; upk2u(r, a, b);
    p0 = expand_h2(a);
    p1 = expand_h2(b);
}

// half-warp tu: this thread's d-half (hb = h*2) for TWO batches, sharing W loads.
__device__ __forceinline__ void tu_half2(const ulonglong2* __restrict__ wr, int hb,
                                         const float* __restrict__ XL,
                                         const float* __restrict__ XH,
                                         u64* aL, u64* aH){
    #pragma unroll
    for (int k = 0; k < 8; k++){
        u64 xkL = pk2(XL[k], XL[k]);
        u64 xkH = pk2(XH[k], XH[k]);
        ulonglong2 w0 = wr[k*4 + hb];
        ulonglong2 w1 = wr[k*4 + hb + 1];
        if (k == 0){
            aL[0] = fmul2(w0.x, xkL); aL[1] = fmul2(w0.y, xkL);
            aL[2] = fmul2(w1.x, xkL); aL[3] = fmul2(w1.y, xkL);
            aH[0] = fmul2(w0.x, xkH); aH[1] = fmul2(w0.y, xkH);
            aH[2] = fmul2(w1.x, xkH); aH[3] = fmul2(w1.y, xkH);
        } else {
            aL[0] = ffma2(w0.x, xkL, aL[0]); aL[1] = ffma2(w0.y, xkL, aL[1]);
            aL[2] = ffma2(w1.x, xkL, aL[2]); aL[3] = ffma2(w1.y, xkL, aL[3]);
            aH[0] = ffma2(w0.x, xkH, aH[0]); aH[1] = ffma2(w0.y, xkH, aH[1]);
            aH[2] = ffma2(w1.x, xkH, aH[2]); aH[3] = ffma2(w1.y, xkH, aH[3]);
        }
    }
}

// ---------------- prep: x re-layout (coalesced) + W transpose ----------------
__global__ void k_prep(const float* __restrict__ x, const float* __restrict__ W){
    __shared__ float t[32][33];
    int xb = blockIdx.x;
    int tid = threadIdx.x;
    if (xb < XBLKS){
        int f0 = (xb % (FDIM/32)) * 32;
        int b0 = (xb / (FDIM/32)) * 32;
        int b_loc = tid >> 5, f_loc = tid & 31;
        t[b_loc][f_loc] = x[(size_t)(b0 + b_loc) * FDIM + f0 + f_loc];
        __syncthreads();
        int i_loc = tid >> 8;
        int r = tid & 255;
        int b = r >> 3, k = r & 7;
        g_xI[(size_t)(f0/8 + i_loc) * XSTRIDE + (b0 + b) * KDIM + k] = t[b][i_loc*8 + k];
    } else {
        int idx = (xb - XBLKS) * 1024 + tid;
        if (idx < WELEMS){
            int k  = idx & 7;
            int d  = (idx >> 3) & 15;
            int ni = idx >> 7;
            g_Wt[(ni << 7) | (k << 4) | d] = W[idx];
        }
    }
}

// ---------------- pass0: compute u_hat (fp32), accumulate s0, store u_hat fp16 ----
// warp = capsule n, half-warp d-split, 2 batches/thread. grid (36, 8), 2 CTAs/SM.
// The two d-halves exchange their "other batch" fp16 pairs via shfl so each
// thread emits ONE hinted 32B store (full row): h=0 -> b_lo, h=1 -> b_hi.
__global__ void __launch_bounds__(320, 2) k_pass0(){
    __shared__ __align__(16) float ws[2][NCAPS*128];

    const int tid   = threadIdx.x;
    const int n     = tid >> 5;
    const int lane  = tid & 31;
    const int l16   = lane & 15;
    const int h     = lane >> 4;
    const int hb    = h * 2;
    const int chunk = blockIdx.x;
    const int bg    = blockIdx.y;
    const int i0    = chunk * 32;
    const int b_lo  = bg * 32 + l16;
    const int b_hi  = b_lo + 16;

    u64 sL[4], sH[4];
    #pragma unroll
    for (int p = 0; p < 4; p++){ sL[p] = 0ull; sH[p] = 0ull; }

    const float* wsrc = g_Wt + ((size_t)(n*IN_CAPS + i0))*128 + lane*4;
    const u32 wdst0 = smemu32(&ws[0][n*128 + lane*4]);
    const u32 wdst1 = smemu32(&ws[1][n*128 + lane*4]);
    const float* xl = g_xI + (size_t)i0 * XSTRIDE + b_lo * KDIM;
    const float* xh = g_xI + (size_t)i0 * XSTRIDE + b_hi * KDIM;
    // this thread stores the full 32B row of batch (b_lo + 16h)
    u64* ub = g_uh + ((size_t)(n*IN_CAPS + i0) * B_TOT + b_lo + 16*h) * 4;

    cpasync16(wdst0, wsrc); cpcommit();
    #pragma unroll 1
    for (int ii = 0; ii < 32; ii++){
        if (ii + 1 < 32) cpasync16((ii & 1) ? wdst0 : wdst1, wsrc + 128);
        cpcommit();
        wsrc += 128;
        cpwait1();
        float4 q0 = *(const float4*)xl, q1 = *(const float4*)(xl + 4);
        float4 r0 = *(const float4*)xh, r1 = *(const float4*)(xh + 4);
        xl += XSTRIDE; xh += XSTRIDE;
        float XL[8] = {q0.x,q0.y,q0.z,q0.w, q1.x,q1.y,q1.z,q1.w};
        float XH[8] = {r0.x,r0.y,r0.z,r0.w, r1.x,r1.y,r1.z,r1.w};
        u64 aL[4], aH[4];
        tu_half2((const ulonglong2*)&ws[ii & 1][n*128], hb, XL, XH, aL, aH);
        #pragma unroll
        for (int p = 0; p < 4; p++){ sL[p] = fadd2(sL[p], aL[p]); sH[p] = fadd2(sH[p], aH[p]); }

        // fp16 pack: own d-half (dq = 2h, 2h+1) of both batches
        u64 pL0 = pk2u(hfp(aL[0]), hfp(aL[1]));
        u64 pL1 = pk2u(hfp(aL[2]), hfp(aL[3]));
        u64 pH0 = pk2u(hfp(aH[0]), hfp(aH[1]));
        u64 pH1 = pk2u(hfp(aH[2]), hfp(aH[3]));
        // exchange the other batch's half across h (shfl_xor 16)
        u64 send0 = h ? pL0 : pH0;
        u64 send1 = h ? pL1 : pH1;
        u64 recv0 = __shfl_xor_sync(0xffffffffu, send0, 16);
        u64 recv1 = __shfl_xor_sync(0xffffffffu, send1, 16);
        // h=0 row(b_lo) = {pL0,pL1,recv0,recv1}; h=1 row(b_hi) = {recv0,recv1,pH0,pH1}
        u64 w0 = h ? recv0 : pL0;
        u64 w1 = h ? recv1 : pL1;
        u64 w2 = h ? pH0   : recv0;
        u64 w3 = h ? pH1   : recv1;
        stg_el(ub, w0, w1, w2, w3);
        ub += (size_t)B_TOT * 4;
    }

    float* spL = g_spart + ((size_t)(chunk*B_TOT + b_lo)*NCAPS + n)*DDIM + 8*h;
    float* spH = g_spart + ((size_t)(chunk*B_TOT + b_hi)*NCAPS + n)*DDIM + 8*h;
    ((ulonglong2*)spL)[0] = make_ulonglong2(sL[0], sL[1]);
    ((ulonglong2*)spL)[1] = make_ulonglong2(sL[2], sL[3]);
    ((ulonglong2*)spH)[0] = make_ulonglong2(sH[0], sH[1]);
    ((ulonglong2*)spH)[1] = make_ulonglong2(sH[2], sH[3]);
}

// ---------------- routed sweep: stream fp16 u_hat, softmax, accumulate ----------
// warp = capsule n, lane = batch. grid (36, 8) = 288 CTAs, 2 CTAs/SM (1 wave).
// TWO i-steps per barrier pair; one hinted 32B load per i. Rows expanded once;
// next pair's loads issue into the freed raw registers. 1/Z from reducer warps.
__global__ void __launch_bounds__(320, 2) k_sweep(){
    __shared__ float ex[4][NCAPS][32];
    __shared__ float zi[4][32];

    const int tid   = threadIdx.x;
    const int n     = tid >> 5;
    const int lane  = tid & 31;
    const int chunk = blockIdx.x;
    const int bg    = blockIdx.y;
    const int i0    = chunk * 32;
    const int b     = bg * 32 + lane;

    u64 v[8];
    {
        const u64* vp = (const u64*)&g_vc[(b*NCAPS + n)*DDIM];
        #pragma unroll
        for (int p = 0; p < 8; p++) v[p] = vp[p];
    }
    u64 s[8];
    #pragma unroll
    for (int p = 0; p < 8; p++) s[p] = 0ull;

    const u64* up = g_uh + ((size_t)(n*IN_CAPS + i0) * B_TOT + b) * 4;
    const size_t ISTEP = (size_t)B_TOT * 4;          // one i in u64 units

    // raw fp16 rows for the current pair (i0, i0+1)
    ulonglong4 R0 = ldg_el(up);
    ulonglong4 R1 = ldg_el(up + ISTEP);
    up += 2 * ISTEP;

    #pragma unroll 1
    for (int ii = 0; ii < 32; ii += 2){
        const int bufA = ((ii >> 1) & 1) * 2;

        // expand current pair ONCE (raw regs become dead after this)
        u64 E0[8], E1[8];
        expand4(R0.x, E0[0], E0[1]); expand4(R0.y, E0[2], E0[3]);
        expand4(R0.z, E0[4], E0[5]); expand4(R0.w, E0[6], E0[7]);
        expand4(R1.x, E1[0], E1[1]); expand4(R1.y, E1[2], E1[3]);
        expand4(R1.z, E1[4], E1[5]); expand4(R1.w, E1[6], E1[7]);

        // issue next pair's loads into the freed raw regs (covered by the
        // dot/exchange/acc phase below)
        if (ii + 2 < 32){
            R0 = ldg_el(up);
            R1 = ldg_el(up + ISTEP);
            up += 2 * ISTEP;
        }

        // dots from the expanded copies
        u64 dA = fmul2(E0[0], v[0]);
        u64 dB = fmul2(E1[0], v[0]);
        #pragma unroll
        for (int p = 1; p < 8; p++){
            dA = ffma2(E0[p], v[p], dA);
            dB = ffma2(E1[p], v[p], dB);
        }
        float lo, hi, fA, fB;
        upk2(dA, lo, hi); fA = lo + hi;
        upk2(dB, lo, hi); fB = lo + hi;
        float eA = __expf(fA), eB = __expf(fB);   // |logit| small: no max-sub
        ex[bufA][n][lane]     = eA;
        ex[bufA + 1][n][lane] = eB;
        __syncthreads();                          // all e's visible

        if (n < 2){                               // reducer warps: one 1/Z per batch
            const int buf = bufA + n;
            float z01 = ex[buf][0][lane] + ex[buf][1][lane];
            float z23 = ex[buf][2][lane] + ex[buf][3][lane];
            float z45 = ex[buf][4][lane] + ex[buf][5][lane];
            float z67 = ex[buf][6][lane] + ex[buf][7][lane];
            float z89 = ex[buf][8][lane] + ex[buf][9][lane];
            zi[buf][lane] = __fdividef(1.0f, ((z01 + z23) + (z45 + z67)) + z89);
        }
        __syncthreads();                          // invZ visible

        float cA = eA * zi[bufA][lane];
        float cB = eB * zi[bufA + 1][lane];
        u64 ccA = pk2(cA, cA), ccB = pk2(cB, cB);
        #pragma unroll
        for (int p = 0; p < 8; p++){
            s[p] = ffma2(E0[p], ccA, s[p]);
            s[p] = ffma2(E1[p], ccB, s[p]);
        }
    }

    float* sp = g_spart + ((size_t)(chunk*B_TOT + b)*NCAPS + n)*DDIM;
    #pragma unroll
    for (int q = 0; q < 4; q++)
        ((ulonglong2*)sp)[q] = make_ulonglong2(s[2*q], s[2*q+1]);
}

// ---------------- reduce partials + squash (2 warps per (b,n), 36 chunks) ------
// MODE 0: vc = v ; MODE 1: vc += v ; MODE 2: out = v
template<int MODE>
__global__ void k_reduce(float* __restrict__ out, float scale){
    __shared__ float red[4][2][16];
    const int tid  = threadIdx.x;
    const int wid  = tid >> 5;
    const int lane = tid & 31;
    const int pib  = wid >> 1;
    const int half = wid & 1;
    const int pair = blockIdx.x * 4 + pib;     // (b,n) in [0, 2560)
    const int d    = lane & 15;
    const int hh   = lane >> 4;
    const size_t base = (size_t)pair * DDIM + d;

    float s = 0.f;
    #pragma unroll
    for (int j = 0; j < 9; j++)
        s += g_spart[(size_t)(half*2 + hh + 4*j) * SND + base];
    s += __shfl_xor_sync(0xffffffffu, s, 16);
    if (lane < 16) red[pib][half][d] = s;
    __syncthreads();
    if (half == 0){
        float st = (red[pib][0][d] + red[pib][1][d]) * scale;
        float sq = st * st;
        sq += __shfl_xor_sync(0xffffffffu, sq, 1);
        sq += __shfl_xor_sync(0xffffffffu, sq, 2);
        sq += __shfl_xor_sync(0xffffffffu, sq, 4);
        sq += __shfl_xor_sync(0xffffffffu, sq, 8);
        float nrm = sqrtf(sq);
        float vv = (sq / (1.0f + sq)) * (st / (nrm + 1e-8f));
        if (lane < 16){
            if (MODE == 0)      g_vc[base] = vv;
            else if (MODE == 1) g_vc[base] += vv;
            else                out[base] = vv;
        }
    }
}

// ---------------- launch ----------------
extern "C" void kernel_launch(void* const* d_in, const int* in_sizes, int n_in,
                              void* d_out, int out_size){
    const float* x = (const float*)d_in[0];
    const float* W = (const float*)d_in[1];
    if (n_in >= 2 && in_sizes[0] == WELEMS){   // defensive order swap
        const float* t = x; x = W; W = t;
    }
    float* out = (float*)d_out;

    k_prep<<<XBLKS + WBLKS, 1024>>>(x, W);

    const int RB = (B_TOT*NCAPS)/4;    // 640 blocks

    k_pass0<<<dim3(P0CH, BGROUPS), 320>>>();
    k_reduce<0><<<RB, 256>>>(nullptr, 0.1f);   // c = softmax(0) = 1/10

    dim3 sg(SWCH, BGROUPS);
    k_sweep<<<sg, 320>>>();
    k_reduce<1><<<RB, 256>>>(nullptr, 1.0f);

    k_sweep<<<sg, 320>>>();
    k_reduce<1><<<RB, 256>>>(nullptr, 1.0f);

    k_sweep<<<sg, 320>>>();
    k_reduce<2><<<RB, 256>>>(out, 1.0f);
}